// round 10
// baseline (speedup 1.0000x reference)
#include <cuda_runtime.h>

// GAT_28295244546247 — v9: fold hoisted to a 1-block pre-kernel; main kernel's
// pre-sync chain = x load + us read + 15-shfl scores + q-accum + publish.
// Analytic collapse (R0): softmax row-constant cancels => identical output rows;
// layer2 softmax exactly uniform; a2_w/a2_b have no effect.

#define NH    8
#define NBLK  128
#define RPB   32
#define NT    512
#define F_OUT 32

__device__ __align__(16) float g_us[NH * 64];  // folded u (written by gat_fold)
__device__ float    g_cs[NH];
__device__ volatile int g_ready = 0;
__device__ float    g_q[NH * 64];              // RED accumulators (reset each replay)
__device__ float    g_Z[NH];
__device__ unsigned g_arrive = 0;
__device__ unsigned g_exit   = 0;

// ---------------------------------------------------------------- fold kernel
__global__ __launch_bounds__(NT) void gat_fold(
    const float* __restrict__ W1, const float* __restrict__ b1,
    const float* __restrict__ a1w, const float* __restrict__ a1b)
{
    __shared__ float W1s[64 * 65];
    __shared__ __align__(16) float a1wjs[NH * 64];
    __shared__ __align__(16) float b1s[64];
    __shared__ float qf[8][NH * 64];

    const int t = threadIdx.x;

    {
        const float4* w4 = (const float4*)W1;
        #pragma unroll
        for (int r = 0; r < 2; r++) {
            int i = t + r * NT;
            float4 v = w4[i];
            int f = i >> 4, k = (i & 15) << 2;
            float* d = &W1s[f * 65 + k];
            d[0] = v.x; d[1] = v.y; d[2] = v.z; d[3] = v.w;
        }
        if (t < 128) {
            int h = t >> 4, q = t & 15;
            ((float4*)a1wjs)[h * 16 + q] = ((const float4*)a1w)[h * 32 + 16 + q];
        } else if (t < 144) {
            ((float4*)b1s)[t - 128] = ((const float4*)b1)[t - 128];
        }
    }
    __syncthreads();

    // fold v2: each W1s value read once, shared across all 8 heads
    {
        const int fg = t >> 6, k = t & 63;
        float acc[NH];
        #pragma unroll
        for (int h = 0; h < NH; h++) acc[h] = 0.f;
        #pragma unroll
        for (int q = 0; q < 2; q++) {
            const int f0 = fg * 8 + q * 4;
            float4 ar[NH];
            #pragma unroll
            for (int h = 0; h < NH; h++)
                ar[h] = ((const float4*)&a1wjs[h * 64 + f0])[0];
            #pragma unroll
            for (int fo = 0; fo < 4; fo++) {
                float w = W1s[(f0 + fo) * 65 + k];
                #pragma unroll
                for (int h = 0; h < NH; h++) {
                    float a = (fo == 0) ? ar[h].x : (fo == 1) ? ar[h].y
                            : (fo == 2) ? ar[h].z : ar[h].w;
                    acc[h] += w * a;
                }
            }
        }
        #pragma unroll
        for (int h = 0; h < NH; h++) qf[fg][h * 64 + k] = acc[h];
    }
    if (t < NH) {
        const float* ar = &a1wjs[t * 64];
        float s0 = 0.f, s1 = 0.f, s2 = 0.f, s3 = 0.f;
        #pragma unroll
        for (int f = 0; f < 64; f += 4) {
            s0 += ar[f + 0] * b1s[f + 0];
            s1 += ar[f + 1] * b1s[f + 1];
            s2 += ar[f + 2] * b1s[f + 2];
            s3 += ar[f + 3] * b1s[f + 3];
        }
        g_cs[t] = a1b[t] + (s0 + s1) + (s2 + s3);
    }
    __syncthreads();
    {
        float s0 = 0.f, s1 = 0.f;
        #pragma unroll
        for (int c = 0; c < 8; c += 2) { s0 += qf[c][t]; s1 += qf[c + 1][t]; }
        g_us[t] = s0 + s1;
    }
    __threadfence();
    __syncthreads();
    if (t == 0) g_ready = 1;
}

// ---------------------------------------------------------------- main kernel
__global__ __launch_bounds__(NT) void gat_main(
    const float* __restrict__ x,  const float* __restrict__ W1,
    const float* __restrict__ b1, const float* __restrict__ W2,
    const float* __restrict__ b2, float* __restrict__ out)
{
    __shared__ float W1s[64 * 65];                  // staged in poll window (tail)
    __shared__ __align__(16) float W2s[F_OUT * 64];
    __shared__ __align__(16) float b1s[64];
    __shared__ __align__(16) float b2s[F_OUT];
    __shared__ __align__(16) float us[NH * 64];
    __shared__ float cs[NH];
    __shared__ __align__(16) float xs[RPB * 68];
    __shared__ __align__(16) float es[RPB * NH];
    __shared__ float qs8[8][NH * 64];
    __shared__ float qbar[64];
    __shared__ float os[64];
    __shared__ float fs[F_OUT];
    __shared__ int   s_last;

    const int t = threadIdx.x;
    const int b = blockIdx.x;
    const int g = t >> 4, u = t & 15;               // 32 rows x 16 threads/row

    // ---- x load (1 float4/thread), park in smem ----
    float4 x4 = ((const float4*)(x + (b * RPB + g) * 64 + u * 4))[0];
    ((float4*)&xs[g * 68])[u] = x4;

    // ---- wait for fold kernel's us/cs ----
    if (t == 0) { while (g_ready == 0) __nanosleep(16); }
    __syncthreads();
    __threadfence();
    if (t < 128) ((float4*)us)[t] = ((const float4*)g_us)[t];
    if (t < NH)  cs[t] = g_cs[t];
    __syncthreads();

    // ---- scores: 16 threads/row, 15-shfl transpose-reduce, exp ----
    {
        float s[NH];
        #pragma unroll
        for (int h = 0; h < NH; h++) {
            float4 u4 = ((const float4*)us)[h * 16 + u];
            s[h] = u4.x * x4.x + u4.y * x4.y + u4.z * x4.z + u4.w * x4.w;
        }
        #pragma unroll
        for (int h = 0; h < NH; h++)                // xor 8: full combine (8 shfl)
            s[h] += __shfl_xor_sync(0xffffffffu, s[h], 8);
        float r4[4];                                // xor 4: head-halve (4 shfl)
        {
            const bool lo = (u & 4) == 0;
            #pragma unroll
            for (int i = 0; i < 4; i++) {
                float give = lo ? s[i + 4] : s[i];
                float got  = __shfl_xor_sync(0xffffffffu, give, 4);
                r4[i] = (lo ? s[i] : s[i + 4]) + got;
            }
        }
        float r2[2];                                // xor 2 (2 shfl)
        {
            const bool lo = (u & 2) == 0;
            #pragma unroll
            for (int i = 0; i < 2; i++) {
                float give = lo ? r4[i + 2] : r4[i];
                float got  = __shfl_xor_sync(0xffffffffu, give, 2);
                r2[i] = (lo ? r4[i] : r4[i + 2]) + got;
            }
        }
        float rf;                                   // xor 1 (1 shfl)
        {
            const bool lo = (u & 1) == 0;
            float give = lo ? r2[1] : r2[0];
            float got  = __shfl_xor_sync(0xffffffffu, give, 1);
            rf = (lo ? r2[0] : r2[1]) + got;
        }
        // lane u (u<8) now holds head u&7's full dot product
        if (u < NH) es[g * 8 + u] = __expf(rf + cs[u]);
    }
    __syncthreads();

    // ---- q partial (f-parallel, 8 j-lanes, float4 es reads) ----
    {
        const int f = t & 63, l = t >> 6;
        float acc[NH];
        #pragma unroll
        for (int h = 0; h < NH; h++) acc[h] = 0.f;
        #pragma unroll
        for (int jj = l; jj < RPB; jj += 8) {
            float4 e0 = ((const float4*)&es[jj * 8])[0];
            float4 e1 = ((const float4*)&es[jj * 8])[1];
            float xv = xs[jj * 68 + f];
            acc[0] += e0.x * xv; acc[1] += e0.y * xv;
            acc[2] += e0.z * xv; acc[3] += e0.w * xv;
            acc[4] += e1.x * xv; acc[5] += e1.y * xv;
            acc[6] += e1.z * xv; acc[7] += e1.w * xv;
        }
        #pragma unroll
        for (int h = 0; h < NH; h++) qs8[l][h * 64 + f] = acc[h];
    }
    __syncthreads();

    // ---- tree-sum + REDG publish ----
    {
        float s0 = 0.f, s1 = 0.f;
        #pragma unroll
        for (int c = 0; c < 8; c += 2) { s0 += qs8[c][t]; s1 += qs8[c + 1][t]; }
        atomicAdd(&g_q[t], s0 + s1);
    }
    if (t < NH) {
        float z0 = 0.f, z1 = 0.f, z2 = 0.f, z3 = 0.f;
        #pragma unroll
        for (int jj = 0; jj < RPB; jj += 4) {
            z0 += es[(jj + 0) * 8 + t];
            z1 += es[(jj + 1) * 8 + t];
            z2 += es[(jj + 2) * 8 + t];
            z3 += es[(jj + 3) * 8 + t];
        }
        atomicAdd(&g_Z[t], (z0 + z1) + (z2 + z3));
    }

    // ---- grid sync; stage ALL tail weights inside the poll window ----
    __threadfence();
    __syncthreads();
    if (t == 0) atomicAdd(&g_arrive, 1);
    {
        const float4* w4 = (const float4*)W1;
        #pragma unroll
        for (int r = 0; r < 2; r++) {
            int i = t + r * NT;
            float4 v = w4[i];
            int f = i >> 4, k = (i & 15) << 2;
            float* d = &W1s[f * 65 + k];
            d[0] = v.x; d[1] = v.y; d[2] = v.z; d[3] = v.w;
        }
        ((float4*)W2s)[t] = ((const float4*)W2)[t];
        if (t < 16)       ((float4*)b1s)[t]      = ((const float4*)b1)[t];
        else if (t < 24)  ((float4*)b2s)[t - 16] = ((const float4*)b2)[t - 16];
    }
    if (t == 0) {
        while (*(volatile unsigned*)&g_arrive < NBLK) __nanosleep(16);
    }
    __syncthreads();
    __threadfence();

    // ---- tail: qbar -> os -> fs (R6 lean structure) ----
    {
        const int f = t >> 3, h = t & 7;
        float v = g_q[h * 64 + f] / g_Z[h];
        v += __shfl_xor_sync(0xffffffffu, v, 1);
        v += __shfl_xor_sync(0xffffffffu, v, 2);
        v += __shfl_xor_sync(0xffffffffu, v, 4);
        if (h == 0) qbar[f] = v * (1.f / NH);
    }
    __syncthreads();
    if (t == 0) s_last = (atomicAdd(&g_exit, 1) == NBLK - 1);  // g_q consumed

    {   // os[m] = elu(lrelu(W1s[m,:].qbar + b1[m])) : 8 threads/output
        const int m = t >> 3, kc = t & 7;
        const float* wr = &W1s[m * 65 + kc * 8];
        const float* q8 = &qbar[kc * 8];
        float s = wr[0] * q8[0] + wr[1] * q8[1] + wr[2] * q8[2] + wr[3] * q8[3]
                + wr[4] * q8[4] + wr[5] * q8[5] + wr[6] * q8[6] + wr[7] * q8[7];
        s += __shfl_xor_sync(0xffffffffu, s, 1);
        s += __shfl_xor_sync(0xffffffffu, s, 2);
        s += __shfl_xor_sync(0xffffffffu, s, 4);
        if (kc == 0) {
            s += b1s[m];
            float lr = s > 0.f ? s : 0.2f * s;
            os[m] = lr > 0.f ? lr : (__expf(lr) - 1.f);
        }
    }
    __syncthreads();
    {   // fs[m] = lrelu(W2s[m,:].os + b2[m]) : 16 threads/output
        const int m = t >> 4, kc = t & 15;
        float4 w = ((const float4*)W2s)[m * 16 + kc];
        const float* o4 = &os[kc * 4];
        float s = w.x * o4[0] + w.y * o4[1] + w.z * o4[2] + w.w * o4[3];
        s += __shfl_xor_sync(0xffffffffu, s, 1);
        s += __shfl_xor_sync(0xffffffffu, s, 2);
        s += __shfl_xor_sync(0xffffffffu, s, 4);
        s += __shfl_xor_sync(0xffffffffu, s, 8);
        if (kc == 0) {
            s += b2s[m];
            fs[m] = s > 0.f ? s : 0.2f * s;
        }
    }
    __syncthreads();

    // ---- output: 32 rows x 32 cols per block = 256 float4 ----
    if (t < 256) {
        int f0 = (t & 7) << 2;
        float4 v = make_float4(fs[f0], fs[f0 + 1], fs[f0 + 2], fs[f0 + 3]);
        ((float4*)out)[b * 256 + t] = v;
    }

    // ---- reset for next graph replay (last exiting block; all reads done) ----
    __syncthreads();
    if (s_last) {
        g_q[t] = 0.f;
        if (t < NH) g_Z[t] = 0.f;
        if (t == 0) { g_arrive = 0; g_exit = 0; g_ready = 0; }
    }
}

extern "C" void kernel_launch(void* const* d_in, const int* in_sizes, int n_in,
                              void* d_out, int out_size) {
    const float* x   = (const float*)d_in[0];
    const float* W1  = (const float*)d_in[1];
    const float* b1  = (const float*)d_in[2];
    const float* a1w = (const float*)d_in[3];
    const float* a1b = (const float*)d_in[4];
    const float* W2  = (const float*)d_in[5];
    const float* b2  = (const float*)d_in[6];
    // d_in[7] (a2_w), d_in[8] (a2_b): provably no effect on output.

    gat_fold<<<1, NT>>>(W1, b1, a1w, a1b);
    gat_main<<<NBLK, NT>>>(x, W1, b1, W2, b2, (float*)d_out);
}

// round 11
// speedup vs baseline: 1.3780x; 1.3780x over previous
#include <cuda_runtime.h>

// GAT_28295244546247 — v10: revert to v8 fused structure (R10 showed the
// separate fold kernel serializes ~4us onto the critical path), plus the
// 15-shfl butterfly score reduction that made v9's main kernel 0.9us faster.
// Analytic collapse (R0): softmax row-constant cancels => identical output rows;
// layer2 softmax exactly uniform; a2_w/a2_b have no effect.

#define NH    8
#define NBLK  128
#define RPB   32
#define NT    512
#define F_OUT 32

__device__ float    g_q[NH * 64];   // zero-init; reset by last exiter each replay
__device__ float    g_Z[NH];
__device__ unsigned g_arrive = 0;
__device__ unsigned g_exit   = 0;

__global__ __launch_bounds__(NT) void gat_fused(
    const float* __restrict__ x,   const float* __restrict__ W1,
    const float* __restrict__ b1,  const float* __restrict__ a1w,
    const float* __restrict__ a1b, const float* __restrict__ W2,
    const float* __restrict__ b2,  float* __restrict__ out)
{
    __shared__ float W1s[64 * 65];                  // padded, conflict-free both axes
    __shared__ __align__(16) float W2s[F_OUT * 64];
    __shared__ __align__(16) float a1wjs[NH * 64];  // a1w[:,64:128]
    __shared__ __align__(16) float b1s[64];
    __shared__ __align__(16) float b2s[F_OUT];
    __shared__ __align__(16) float us[NH * 64];     // folded u [h][k]
    __shared__ float cs[NH];
    __shared__ __align__(16) float xs[RPB * 68];    // stride 68: float4-aligned rows
    __shared__ __align__(16) float es[RPB * NH];
    __shared__ float qs8[8][NH * 64];               // 8-copy partials (fold & q-accum)
    __shared__ float qbar[64];
    __shared__ float os[64];
    __shared__ float fs[F_OUT];
    __shared__ int   s_last;

    const int t = threadIdx.x;
    const int b = blockIdx.x;
    const int g = t >> 4, u = t & 15;               // 32 rows x 16 threads/row

    // ---- phase 0: x load (1 float4/thread) + weight staging ----
    float4 x4 = ((const float4*)(x + (b * RPB + g) * 64 + u * 4))[0];
    {
        const float4* w4 = (const float4*)W1;
        #pragma unroll
        for (int r = 0; r < 2; r++) {
            int i = t + r * NT;
            float4 v = w4[i];
            int f = i >> 4, k = (i & 15) << 2;
            float* d = &W1s[f * 65 + k];
            d[0] = v.x; d[1] = v.y; d[2] = v.z; d[3] = v.w;
        }
        if (t < 128) {
            int h = t >> 4, q = t & 15;
            ((float4*)a1wjs)[h * 16 + q] = ((const float4*)a1w)[h * 32 + 16 + q];
        } else if (t < 144) {
            ((float4*)b1s)[t - 128] = ((const float4*)b1)[t - 128];
        }
        ((float4*)&xs[g * 68])[u] = x4;
    }
    __syncthreads();

    // ---- phase 1: fold v2 — each W1s value read ONCE, shared across 8 heads ----
    {
        const int fg = t >> 6, k = t & 63;
        float acc[NH];
        #pragma unroll
        for (int h = 0; h < NH; h++) acc[h] = 0.f;
        #pragma unroll
        for (int q = 0; q < 2; q++) {               // two f-quads
            const int f0 = fg * 8 + q * 4;
            float4 ar[NH];                           // broadcast LDS.128 per head
            #pragma unroll
            for (int h = 0; h < NH; h++)
                ar[h] = ((const float4*)&a1wjs[h * 64 + f0])[0];
            #pragma unroll
            for (int fo = 0; fo < 4; fo++) {
                float w = W1s[(f0 + fo) * 65 + k];
                #pragma unroll
                for (int h = 0; h < NH; h++) {
                    float a = (fo == 0) ? ar[h].x : (fo == 1) ? ar[h].y
                            : (fo == 2) ? ar[h].z : ar[h].w;
                    acc[h] += w * a;
                }
            }
        }
        #pragma unroll
        for (int h = 0; h < NH; h++) qs8[fg][h * 64 + k] = acc[h];
    }
    if (t < NH) {                                    // c[h] = a1b + ar.b1 (4-acc)
        const float* ar = &a1wjs[t * 64];
        float s0 = 0.f, s1 = 0.f, s2 = 0.f, s3 = 0.f;
        #pragma unroll
        for (int f = 0; f < 64; f += 4) {
            s0 += ar[f + 0] * b1s[f + 0];
            s1 += ar[f + 1] * b1s[f + 1];
            s2 += ar[f + 2] * b1s[f + 2];
            s3 += ar[f + 3] * b1s[f + 3];
        }
        cs[t] = a1b[t] + (s0 + s1) + (s2 + s3);
    }
    __syncthreads();

    // ---- phase 2: tree-sum fold partials -> us ----
    {
        float s0 = 0.f, s1 = 0.f;
        #pragma unroll
        for (int c = 0; c < 8; c += 2) { s0 += qs8[c][t]; s1 += qs8[c + 1][t]; }
        us[t] = s0 + s1;
    }
    __syncthreads();

    // ---- phase 3: scores — 16 threads/row, 15-shfl butterfly, exp ----
    {
        float s[NH];
        #pragma unroll
        for (int h = 0; h < NH; h++) {
            float4 u4 = ((const float4*)us)[h * 16 + u];
            s[h] = u4.x * x4.x + u4.y * x4.y + u4.z * x4.z + u4.w * x4.w;
        }
        #pragma unroll
        for (int h = 0; h < NH; h++)                // xor 8: full combine (8 shfl)
            s[h] += __shfl_xor_sync(0xffffffffu, s[h], 8);
        float r4[4];                                // xor 4: head-halve (4 shfl)
        {
            const bool lo = (u & 4) == 0;
            #pragma unroll
            for (int i = 0; i < 4; i++) {
                float give = lo ? s[i + 4] : s[i];
                float got  = __shfl_xor_sync(0xffffffffu, give, 4);
                r4[i] = (lo ? s[i] : s[i + 4]) + got;
            }
        }
        float r2[2];                                // xor 2 (2 shfl)
        {
            const bool lo = (u & 2) == 0;
            #pragma unroll
            for (int i = 0; i < 2; i++) {
                float give = lo ? r4[i + 2] : r4[i];
                float got  = __shfl_xor_sync(0xffffffffu, give, 2);
                r2[i] = (lo ? r4[i] : r4[i + 2]) + got;
            }
        }
        float rf;                                   // xor 1 (1 shfl)
        {
            const bool lo = (u & 1) == 0;
            float give = lo ? r2[1] : r2[0];
            float got  = __shfl_xor_sync(0xffffffffu, give, 1);
            rf = (lo ? r2[0] : r2[1]) + got;
        }
        if (u < NH) es[g * 8 + u] = __expf(rf + cs[u]);
    }
    __syncthreads();

    // ---- phase 4: q partial (f-parallel, 8 j-lanes, float4 es reads) ----
    {
        const int f = t & 63, l = t >> 6;
        float acc[NH];
        #pragma unroll
        for (int h = 0; h < NH; h++) acc[h] = 0.f;
        #pragma unroll
        for (int jj = l; jj < RPB; jj += 8) {
            float4 e0 = ((const float4*)&es[jj * 8])[0];
            float4 e1 = ((const float4*)&es[jj * 8])[1];
            float xv = xs[jj * 68 + f];
            acc[0] += e0.x * xv; acc[1] += e0.y * xv;
            acc[2] += e0.z * xv; acc[3] += e0.w * xv;
            acc[4] += e1.x * xv; acc[5] += e1.y * xv;
            acc[6] += e1.z * xv; acc[7] += e1.w * xv;
        }
        #pragma unroll
        for (int h = 0; h < NH; h++) qs8[l][h * 64 + f] = acc[h];
    }
    __syncthreads();

    // ---- phase 5: tree-sum + REDG publish ----
    {
        float s0 = 0.f, s1 = 0.f;
        #pragma unroll
        for (int c = 0; c < 8; c += 2) { s0 += qs8[c][t]; s1 += qs8[c + 1][t]; }
        atomicAdd(&g_q[t], s0 + s1);
    }
    if (t < NH) {
        float z0 = 0.f, z1 = 0.f, z2 = 0.f, z3 = 0.f;
        #pragma unroll
        for (int jj = 0; jj < RPB; jj += 4) {
            z0 += es[(jj + 0) * 8 + t];
            z1 += es[(jj + 1) * 8 + t];
            z2 += es[(jj + 2) * 8 + t];
            z3 += es[(jj + 3) * 8 + t];
        }
        atomicAdd(&g_Z[t], (z0 + z1) + (z2 + z3));
    }

    // ---- grid sync; stage W2/b2 inside the poll window ----
    __threadfence();
    __syncthreads();
    if (t == 0) atomicAdd(&g_arrive, 1);
    ((float4*)W2s)[t] = ((const float4*)W2)[t];
    if (t < NH) ((float4*)b2s)[t] = ((const float4*)b2)[t];
    if (t == 0) {
        while (*(volatile unsigned*)&g_arrive < NBLK) __nanosleep(32);
    }
    __syncthreads();
    __threadfence();

    // ---- tail (R6 lean structure) ----
    {
        const int f = t >> 3, h = t & 7;
        float v = g_q[h * 64 + f] / g_Z[h];
        v += __shfl_xor_sync(0xffffffffu, v, 1);
        v += __shfl_xor_sync(0xffffffffu, v, 2);
        v += __shfl_xor_sync(0xffffffffu, v, 4);
        if (h == 0) qbar[f] = v * (1.f / NH);
    }
    __syncthreads();
    if (t == 0) s_last = (atomicAdd(&g_exit, 1) == NBLK - 1);  // g_q consumed

    {   // os[m] = elu(lrelu(W1s[m,:].qbar + b1[m])) : 8 threads/output
        const int m = t >> 3, kc = t & 7;
        const float* wr = &W1s[m * 65 + kc * 8];
        const float* q8 = &qbar[kc * 8];
        float s = wr[0] * q8[0] + wr[1] * q8[1] + wr[2] * q8[2] + wr[3] * q8[3]
                + wr[4] * q8[4] + wr[5] * q8[5] + wr[6] * q8[6] + wr[7] * q8[7];
        s += __shfl_xor_sync(0xffffffffu, s, 1);
        s += __shfl_xor_sync(0xffffffffu, s, 2);
        s += __shfl_xor_sync(0xffffffffu, s, 4);
        if (kc == 0) {
            s += b1s[m];
            float lr = s > 0.f ? s : 0.2f * s;
            os[m] = lr > 0.f ? lr : (__expf(lr) - 1.f);
        }
    }
    __syncthreads();
    {   // fs[m] = lrelu(W2s[m,:].os + b2[m]) : 16 threads/output
        const int m = t >> 4, kc = t & 15;
        float4 w = ((const float4*)W2s)[m * 16 + kc];
        const float* o4 = &os[kc * 4];
        float s = w.x * o4[0] + w.y * o4[1] + w.z * o4[2] + w.w * o4[3];
        s += __shfl_xor_sync(0xffffffffu, s, 1);
        s += __shfl_xor_sync(0xffffffffu, s, 2);
        s += __shfl_xor_sync(0xffffffffu, s, 4);
        s += __shfl_xor_sync(0xffffffffu, s, 8);
        if (kc == 0) {
            s += b2s[m];
            fs[m] = s > 0.f ? s : 0.2f * s;
        }
    }
    __syncthreads();

    // ---- output: 32 rows x 32 cols per block = 256 float4 ----
    if (t < 256) {
        int f0 = (t & 7) << 2;
        float4 v = make_float4(fs[f0], fs[f0 + 1], fs[f0 + 2], fs[f0 + 3]);
        ((float4*)out)[b * 256 + t] = v;
    }

    // ---- reset for next graph replay (last exiting block; all reads done) ----
    __syncthreads();
    if (s_last) {
        g_q[t] = 0.f;
        if (t < NH) g_Z[t] = 0.f;
        if (t == 0) { g_arrive = 0; g_exit = 0; }
    }
}

extern "C" void kernel_launch(void* const* d_in, const int* in_sizes, int n_in,
                              void* d_out, int out_size) {
    const float* x   = (const float*)d_in[0];
    const float* W1  = (const float*)d_in[1];
    const float* b1  = (const float*)d_in[2];
    const float* a1w = (const float*)d_in[3];
    const float* a1b = (const float*)d_in[4];
    const float* W2  = (const float*)d_in[5];
    const float* b2  = (const float*)d_in[6];
    // d_in[7] (a2_w), d_in[8] (a2_b): provably no effect on output.

    gat_fused<<<NBLK, NT>>>(x, W1, b1, a1w, a1b, W2, b2, (float*)d_out);
}